// round 4
// baseline (speedup 1.0000x reference)
#include <cuda_runtime.h>

#define DD 128
#define NODES_MAX 50000
#define EDGES_MAX 800000
#define SCAN_THREADS 1024
#define SCAN_CHUNK 49   // 1024 * 49 = 50176 >= 50000

// Device scratch (allocation-free rule -> __device__ globals)
__device__ float g_agg[NODES_MAX * DD];
__device__ int   g_deg[NODES_MAX];
__device__ int   g_off[NODES_MAX];     // exclusive prefix (row start)
__device__ int   g_cur[NODES_MAX];     // fill cursors
__device__ int   g_csr[EDGES_MAX];     // src indices grouped by dst

// ---------------------------------------------------------------------------
// 1) zero degree counters
// ---------------------------------------------------------------------------
__global__ void zero_deg_kernel(int n) {
    int i = blockIdx.x * blockDim.x + threadIdx.x;
    if (i < n) g_deg[i] = 0;
}

// ---------------------------------------------------------------------------
// 2) histogram of dst
// ---------------------------------------------------------------------------
__global__ void hist_kernel(const int* __restrict__ dst, int n_edges, int n_nodes) {
    int e = blockIdx.x * blockDim.x + threadIdx.x;
    if (e >= n_edges) return;
    int d = __ldg(&dst[e]);
    if ((unsigned)d < (unsigned)n_nodes) atomicAdd(&g_deg[d], 1);
}

// ---------------------------------------------------------------------------
// 3) single-block exclusive scan of degrees -> offsets + cursors
// ---------------------------------------------------------------------------
__global__ __launch_bounds__(SCAN_THREADS)
void scan_kernel(int n) {
    __shared__ int partials[SCAN_THREADS];
    int t = threadIdx.x;
    int start = t * SCAN_CHUNK;
    int end = min(start + SCAN_CHUNK, n);

    int s = 0;
    for (int i = start; i < end; i++) s += g_deg[i];
    partials[t] = s;
    __syncthreads();

    // Hillis-Steele inclusive scan in smem
    #pragma unroll
    for (int off = 1; off < SCAN_THREADS; off <<= 1) {
        int v = (t >= off) ? partials[t - off] : 0;
        __syncthreads();
        partials[t] += v;
        __syncthreads();
    }

    int base = (t == 0) ? 0 : partials[t - 1];  // exclusive prefix of my chunk
    for (int i = start; i < end; i++) {
        g_off[i] = base;
        g_cur[i] = base;
        base += g_deg[i];
    }
}

// ---------------------------------------------------------------------------
// 4) fill CSR: group src by dst
// ---------------------------------------------------------------------------
__global__ void fill_kernel(const int* __restrict__ src,
                            const int* __restrict__ dst,
                            int n_edges, int n_nodes) {
    int e = blockIdx.x * blockDim.x + threadIdx.x;
    if (e >= n_edges) return;
    int d = __ldg(&dst[e]);
    int s = __ldg(&src[e]);
    if ((unsigned)d >= (unsigned)n_nodes || (unsigned)s >= (unsigned)n_nodes) return;
    int pos = atomicAdd(&g_cur[d], 1);
    g_csr[pos] = s;
}

// ---------------------------------------------------------------------------
// 5) gather-aggregate: one warp per node, accumulate in registers, single write
// ---------------------------------------------------------------------------
__global__ __launch_bounds__(256)
void gather_agg_kernel(const float* __restrict__ x, int n_nodes) {
    int node = (blockIdx.x * blockDim.x + threadIdx.x) >> 5;
    int lane = threadIdx.x & 31;
    if (node >= n_nodes) return;

    int beg = g_off[node];
    int deg = g_deg[node];

    float4 acc = make_float4(0.f, 0.f, 0.f, 0.f);

    for (int j0 = 0; j0 < deg; j0 += 32) {
        int j = j0 + lane;
        int sidx = (j < deg) ? g_csr[beg + j] : 0;
        int m = min(32, deg - j0);
        // unroll by 2 for memory-level parallelism on the row gathers
        int t = 0;
        for (; t + 1 < m; t += 2) {
            int s0 = __shfl_sync(0xffffffff, sidx, t);
            int s1 = __shfl_sync(0xffffffff, sidx, t + 1);
            float4 v0 = __ldg(reinterpret_cast<const float4*>(
                x + (size_t)s0 * DD + lane * 4));
            float4 v1 = __ldg(reinterpret_cast<const float4*>(
                x + (size_t)s1 * DD + lane * 4));
            acc.x += v0.x + v1.x; acc.y += v0.y + v1.y;
            acc.z += v0.z + v1.z; acc.w += v0.w + v1.w;
        }
        if (t < m) {
            int s0 = __shfl_sync(0xffffffff, sidx, t);
            float4 v0 = __ldg(reinterpret_cast<const float4*>(
                x + (size_t)s0 * DD + lane * 4));
            acc.x += v0.x; acc.y += v0.y; acc.z += v0.z; acc.w += v0.w;
        }
    }

    *reinterpret_cast<float4*>(g_agg + (size_t)node * DD + lane * 4) = acc;
}

// ---------------------------------------------------------------------------
// 6) out = relu(agg @ W^T) + x
// ---------------------------------------------------------------------------
#define WT_LD 132
#define WARPS_PER_BLOCK 8
#define ROWS_PER_WARP 4

__global__ __launch_bounds__(256)
void gemm_relu_res_kernel(const float* __restrict__ x,
                          const float* __restrict__ W,
                          float* __restrict__ out,
                          int n_rows) {
    extern __shared__ float smem[];
    float* Wt = smem;                              // [128][WT_LD]
    float* rowbuf = smem + DD * WT_LD;             // [WARPS][4][128]

    for (int idx = threadIdx.x; idx < DD * DD; idx += blockDim.x) {
        int j = idx & (DD - 1);
        int k = idx >> 7;
        Wt[k * WT_LD + j] = W[j * DD + k];
    }
    __syncthreads();

    const int warp = threadIdx.x >> 5;
    const int lane = threadIdx.x & 31;
    float* rb = rowbuf + warp * (ROWS_PER_WARP * DD);

    const int warps_total = gridDim.x * WARPS_PER_BLOCK;
    const int gwarp = blockIdx.x * WARPS_PER_BLOCK + warp;

    for (int r0 = gwarp * ROWS_PER_WARP; r0 < n_rows;
         r0 += warps_total * ROWS_PER_WARP) {

        __syncwarp();
        #pragma unroll
        for (int r = 0; r < ROWS_PER_WARP; r++) {
            int row = r0 + r;
            if (row < n_rows) {
                float4 v = *reinterpret_cast<const float4*>(
                    g_agg + (size_t)row * DD + lane * 4);
                *reinterpret_cast<float4*>(rb + r * DD + lane * 4) = v;
            }
        }
        __syncwarp();

        float4 acc0 = make_float4(0.f, 0.f, 0.f, 0.f);
        float4 acc1 = acc0, acc2 = acc0, acc3 = acc0;

        #pragma unroll 8
        for (int k = 0; k < DD; k += 4) {
            float4 a0 = *reinterpret_cast<const float4*>(rb + 0 * DD + k);
            float4 a1 = *reinterpret_cast<const float4*>(rb + 1 * DD + k);
            float4 a2 = *reinterpret_cast<const float4*>(rb + 2 * DD + k);
            float4 a3 = *reinterpret_cast<const float4*>(rb + 3 * DD + k);
            const float* pa0 = reinterpret_cast<const float*>(&a0);
            const float* pa1 = reinterpret_cast<const float*>(&a1);
            const float* pa2 = reinterpret_cast<const float*>(&a2);
            const float* pa3 = reinterpret_cast<const float*>(&a3);

            #pragma unroll
            for (int kk = 0; kk < 4; kk++) {
                float4 w = *reinterpret_cast<const float4*>(
                    Wt + (k + kk) * WT_LD + lane * 4);
                float b0 = pa0[kk], b1 = pa1[kk], b2 = pa2[kk], b3 = pa3[kk];
                acc0.x += b0 * w.x; acc0.y += b0 * w.y;
                acc0.z += b0 * w.z; acc0.w += b0 * w.w;
                acc1.x += b1 * w.x; acc1.y += b1 * w.y;
                acc1.z += b1 * w.z; acc1.w += b1 * w.w;
                acc2.x += b2 * w.x; acc2.y += b2 * w.y;
                acc2.z += b2 * w.z; acc2.w += b2 * w.w;
                acc3.x += b3 * w.x; acc3.y += b3 * w.y;
                acc3.z += b3 * w.z; acc3.w += b3 * w.w;
            }
        }

        float4 accs[4] = {acc0, acc1, acc2, acc3};
        #pragma unroll
        for (int r = 0; r < ROWS_PER_WARP; r++) {
            int row = r0 + r;
            if (row >= n_rows) break;
            float4 a = accs[r];
            float4 xr = *reinterpret_cast<const float4*>(
                x + (size_t)row * DD + lane * 4);
            float4 res;
            res.x = fmaxf(a.x, 0.f) + xr.x;
            res.y = fmaxf(a.y, 0.f) + xr.y;
            res.z = fmaxf(a.z, 0.f) + xr.z;
            res.w = fmaxf(a.w, 0.f) + xr.w;
            *reinterpret_cast<float4*>(out + (size_t)row * DD + lane * 4) = res;
        }
    }
}

// ---------------------------------------------------------------------------
// Launch
// ---------------------------------------------------------------------------
extern "C" void kernel_launch(void* const* d_in, const int* in_sizes, int n_in,
                              void* d_out, int out_size) {
    const float* x   = (const float*)d_in[0];      // [N, 128] f32
    const float* W   = (const float*)d_in[1];      // [128, 128] f32
    const int*   src = (const int*)d_in[2];        // [E] int32
    const int*   dst = (const int*)d_in[3];        // [E] int32
    float*       out = (float*)d_out;              // [N, 128] f32

    const int n_nodes = in_sizes[0] / DD;
    const int n_edges = in_sizes[2];

    // CSR build (all device-side, graph-capturable)
    zero_deg_kernel<<<(n_nodes + 255) / 256, 256>>>(n_nodes);
    hist_kernel<<<(n_edges + 255) / 256, 256>>>(dst, n_edges, n_nodes);
    scan_kernel<<<1, SCAN_THREADS>>>(n_nodes);
    fill_kernel<<<(n_edges + 255) / 256, 256>>>(src, dst, n_edges, n_nodes);

    // Gather-only aggregation (no atomics, no zero-init of agg)
    int gw_blocks = (n_nodes * 32 + 255) / 256;
    gather_agg_kernel<<<gw_blocks, 256>>>(x, n_nodes);

    // Fused GEMM + relu + residual
    size_t smem = (DD * WT_LD + WARPS_PER_BLOCK * ROWS_PER_WARP * DD) * sizeof(float);
    cudaFuncSetAttribute(gemm_relu_res_kernel,
                         cudaFuncAttributeMaxDynamicSharedMemorySize, (int)smem);
    gemm_relu_res_kernel<<<296, 256, smem>>>(x, W, out, n_nodes);
}

// round 5
// speedup vs baseline: 1.3950x; 1.3950x over previous
#include <cuda_runtime.h>

#define DD 128
#define NODES_MAX 50000

// Scratch: aggregated neighbor features (allocation-free rule -> __device__ global)
__device__ float g_agg[NODES_MAX * DD];

// ---------------------------------------------------------------------------
// Kernel 1: zero the aggregation buffer
// ---------------------------------------------------------------------------
__global__ void zero_agg_kernel(int n4) {
    float4 z = make_float4(0.f, 0.f, 0.f, 0.f);
    for (int i = blockIdx.x * blockDim.x + threadIdx.x; i < n4;
         i += gridDim.x * blockDim.x) {
        reinterpret_cast<float4*>(g_agg)[i] = z;
    }
}

// ---------------------------------------------------------------------------
// Kernel 2: scatter-add  agg[dst] += x[src]
// Grid-stride; each warp processes batches of 8 edges:
//  - 16 broadcast index loads hoisted
//  - 8 independent LDG.128 row-gathers in flight (MLP=8)
//  - 8 float4 RED atomics (fire-and-forget)
// ---------------------------------------------------------------------------
#define EPW 8   // edges per warp-batch

__global__ __launch_bounds__(256)
void scatter_add_kernel(const float* __restrict__ x,
                        const int* __restrict__ src,
                        const int* __restrict__ dst,
                        int n_edges, int n_nodes) {
    const int lane = threadIdx.x & 31;
    const int gwarp = (blockIdx.x * blockDim.x + threadIdx.x) >> 5;
    const int nwarps = (gridDim.x * blockDim.x) >> 5;

    for (int base = gwarp * EPW; base < n_edges; base += nwarps * EPW) {
        const int cnt = min(EPW, n_edges - base);

        int s[EPW], d[EPW];
        #pragma unroll
        for (int i = 0; i < EPW; i++) {
            int e = (i < cnt) ? (base + i) : base;
            s[i] = __ldg(&src[e]);   // broadcast (1 sector)
            d[i] = __ldg(&dst[e]);
            if ((unsigned)s[i] >= (unsigned)n_nodes) s[i] = 0;  // fail-soft
        }

        float4 v[EPW];
        #pragma unroll
        for (int i = 0; i < EPW; i++) {
            v[i] = __ldg(reinterpret_cast<const float4*>(
                       x + (size_t)s[i] * DD) + lane);
        }

        #pragma unroll
        for (int i = 0; i < EPW; i++) {
            if (i < cnt && (unsigned)d[i] < (unsigned)n_nodes) {
                atomicAdd(reinterpret_cast<float4*>(
                              g_agg + (size_t)d[i] * DD) + lane, v[i]);
            }
        }
    }
}

// ---------------------------------------------------------------------------
// Kernel 3: out = relu(agg @ W^T) + x   with packed fma.rn.f32x2
// Wt[k][j] in smem (pad 132). w float4 rows reinterpret directly as two
// pre-packed f32x2 operands; broadcast scalar packed once per (row,kk).
// ---------------------------------------------------------------------------
#define WT_LD 132
#define WARPS_PER_BLOCK 8
#define ROWS_PER_WARP 4

__device__ __forceinline__ unsigned long long pack_dup(float b) {
    unsigned long long r;
    asm("mov.b64 %0, {%1, %1};" : "=l"(r) : "f"(b));
    return r;
}
__device__ __forceinline__ void fma2(unsigned long long& acc,
                                     unsigned long long a,
                                     unsigned long long b) {
    asm("fma.rn.f32x2 %0, %1, %2, %0;" : "+l"(acc) : "l"(a), "l"(b));
}
__device__ __forceinline__ float2 unpack2(unsigned long long v) {
    float lo, hi;
    asm("mov.b64 {%0, %1}, %2;" : "=f"(lo), "=f"(hi) : "l"(v));
    return make_float2(lo, hi);
}

__global__ __launch_bounds__(256)
void gemm_relu_res_kernel(const float* __restrict__ x,
                          const float* __restrict__ W,
                          float* __restrict__ out,
                          int n_rows) {
    extern __shared__ float smem[];
    float* Wt = smem;                              // [128][WT_LD]
    float* rowbuf = smem + DD * WT_LD;             // [WARPS][4][128]

    for (int idx = threadIdx.x; idx < DD * DD; idx += blockDim.x) {
        int j = idx & (DD - 1);
        int k = idx >> 7;
        Wt[k * WT_LD + j] = W[j * DD + k];
    }
    __syncthreads();

    const int warp = threadIdx.x >> 5;
    const int lane = threadIdx.x & 31;
    float* rb = rowbuf + warp * (ROWS_PER_WARP * DD);

    const int warps_total = gridDim.x * WARPS_PER_BLOCK;
    const int gwarp = blockIdx.x * WARPS_PER_BLOCK + warp;

    for (int r0 = gwarp * ROWS_PER_WARP; r0 < n_rows;
         r0 += warps_total * ROWS_PER_WARP) {

        __syncwarp();
        #pragma unroll
        for (int r = 0; r < ROWS_PER_WARP; r++) {
            int row = r0 + r;
            if (row < n_rows) {
                float4 v = *reinterpret_cast<const float4*>(
                    g_agg + (size_t)row * DD + lane * 4);
                *reinterpret_cast<float4*>(rb + r * DD + lane * 4) = v;
            }
        }
        __syncwarp();

        // acc[r] pairs: {out[lane*4], out[lane*4+1]} and {+2, +3}
        unsigned long long acc01[ROWS_PER_WARP] = {0ull, 0ull, 0ull, 0ull};
        unsigned long long acc23[ROWS_PER_WARP] = {0ull, 0ull, 0ull, 0ull};

        #pragma unroll 4
        for (int k = 0; k < DD; k += 4) {
            float4 a0 = *reinterpret_cast<const float4*>(rb + 0 * DD + k);
            float4 a1 = *reinterpret_cast<const float4*>(rb + 1 * DD + k);
            float4 a2 = *reinterpret_cast<const float4*>(rb + 2 * DD + k);
            float4 a3 = *reinterpret_cast<const float4*>(rb + 3 * DD + k);
            const float* pa[4] = {
                reinterpret_cast<const float*>(&a0),
                reinterpret_cast<const float*>(&a1),
                reinterpret_cast<const float*>(&a2),
                reinterpret_cast<const float*>(&a3)};

            #pragma unroll
            for (int kk = 0; kk < 4; kk++) {
                // w row loaded as 2 pre-packed f32x2 values
                ulonglong2 w = *reinterpret_cast<const ulonglong2*>(
                    Wt + (k + kk) * WT_LD + lane * 4);
                #pragma unroll
                for (int r = 0; r < ROWS_PER_WARP; r++) {
                    unsigned long long bb = pack_dup(pa[r][kk]);
                    fma2(acc01[r], w.x, bb);
                    fma2(acc23[r], w.y, bb);
                }
            }
        }

        #pragma unroll
        for (int r = 0; r < ROWS_PER_WARP; r++) {
            int row = r0 + r;
            if (row >= n_rows) break;
            float2 p01 = unpack2(acc01[r]);
            float2 p23 = unpack2(acc23[r]);
            float4 xr = *reinterpret_cast<const float4*>(
                x + (size_t)row * DD + lane * 4);
            float4 res;
            res.x = fmaxf(p01.x, 0.f) + xr.x;
            res.y = fmaxf(p01.y, 0.f) + xr.y;
            res.z = fmaxf(p23.x, 0.f) + xr.z;
            res.w = fmaxf(p23.y, 0.f) + xr.w;
            *reinterpret_cast<float4*>(out + (size_t)row * DD + lane * 4) = res;
        }
    }
}

// ---------------------------------------------------------------------------
// Launch
// ---------------------------------------------------------------------------
extern "C" void kernel_launch(void* const* d_in, const int* in_sizes, int n_in,
                              void* d_out, int out_size) {
    const float* x   = (const float*)d_in[0];      // [N, 128] f32
    const float* W   = (const float*)d_in[1];      // [128, 128] f32
    const int*   src = (const int*)d_in[2];        // [E] int32
    const int*   dst = (const int*)d_in[3];        // [E] int32
    float*       out = (float*)d_out;              // [N, 128] f32

    const int n_nodes = in_sizes[0] / DD;
    const int n_edges = in_sizes[2];

    // 1) zero agg
    zero_agg_kernel<<<592, 256>>>(n_nodes * DD / 4);

    // 2) scatter-add, 8 edges per warp-batch, grid-stride (~2 batches/warp)
    int nwarps_needed = (n_edges + EPW - 1) / EPW;
    int blocks = (nwarps_needed / 2 + 7) / 8;          // 8 warps per block
    if (blocks > 6144) blocks = 6144;
    if (blocks < 148) blocks = 148;
    scatter_add_kernel<<<blocks, 256>>>(x, src, dst, n_edges, n_nodes);

    // 3) fused GEMM + relu + residual (f32x2 packed FMA)
    size_t smem = (DD * WT_LD + WARPS_PER_BLOCK * ROWS_PER_WARP * DD) * sizeof(float);
    cudaFuncSetAttribute(gemm_relu_res_kernel,
                         cudaFuncAttributeMaxDynamicSharedMemorySize, (int)smem);
    gemm_relu_res_kernel<<<296, 256, smem>>>(x, W, out, n_nodes);
}

// round 6
// speedup vs baseline: 1.3960x; 1.0007x over previous
#include <cuda_runtime.h>

#define DD 128
#define NODES_MAX 50000

// Scratch: aggregated neighbor features (allocation-free rule -> __device__ global)
__device__ float g_agg[NODES_MAX * DD];

// ---------------------------------------------------------------------------
// Kernel 1: zero the aggregation buffer
// ---------------------------------------------------------------------------
__global__ void zero_agg_kernel(int n4) {
    float4 z = make_float4(0.f, 0.f, 0.f, 0.f);
    for (int i = blockIdx.x * blockDim.x + threadIdx.x; i < n4;
         i += gridDim.x * blockDim.x) {
        reinterpret_cast<float4*>(g_agg)[i] = z;
    }
}

// ---------------------------------------------------------------------------
// Kernel 2: scatter-add  agg[dst] += x[src]
// Grid-stride; each warp processes batches of 8 edges:
//  - 16 broadcast index loads hoisted
//  - 8 independent LDG.128 row-gathers in flight (MLP=8)
//  - 8 float4 RED atomics (fire-and-forget)
// ---------------------------------------------------------------------------
#define EPW 8   // edges per warp-batch

__global__ __launch_bounds__(256)
void scatter_add_kernel(const float* __restrict__ x,
                        const int* __restrict__ src,
                        const int* __restrict__ dst,
                        int n_edges, int n_nodes) {
    const int lane = threadIdx.x & 31;
    const int gwarp = (blockIdx.x * blockDim.x + threadIdx.x) >> 5;
    const int nwarps = (gridDim.x * blockDim.x) >> 5;

    for (int base = gwarp * EPW; base < n_edges; base += nwarps * EPW) {
        const int cnt = min(EPW, n_edges - base);

        int s[EPW], d[EPW];
        #pragma unroll
        for (int i = 0; i < EPW; i++) {
            int e = (i < cnt) ? (base + i) : base;
            s[i] = __ldg(&src[e]);   // broadcast (1 sector)
            d[i] = __ldg(&dst[e]);
            if ((unsigned)s[i] >= (unsigned)n_nodes) s[i] = 0;  // fail-soft
        }

        float4 v[EPW];
        #pragma unroll
        for (int i = 0; i < EPW; i++) {
            v[i] = __ldg(reinterpret_cast<const float4*>(
                       x + (size_t)s[i] * DD) + lane);
        }

        #pragma unroll
        for (int i = 0; i < EPW; i++) {
            if (i < cnt && (unsigned)d[i] < (unsigned)n_nodes) {
                atomicAdd(reinterpret_cast<float4*>(
                              g_agg + (size_t)d[i] * DD) + lane, v[i]);
            }
        }
    }
}

// ---------------------------------------------------------------------------
// Kernel 3: out = relu(agg @ W^T) + x   with packed fma.rn.f32x2
// Wt[k][j] in smem (pad 132). w float4 rows reinterpret directly as two
// pre-packed f32x2 operands; broadcast scalar packed once per (row,kk).
// ---------------------------------------------------------------------------
#define WT_LD 132
#define WARPS_PER_BLOCK 8
#define ROWS_PER_WARP 4

__device__ __forceinline__ unsigned long long pack_dup(float b) {
    unsigned long long r;
    asm("mov.b64 %0, {%1, %1};" : "=l"(r) : "f"(b));
    return r;
}
__device__ __forceinline__ void fma2(unsigned long long& acc,
                                     unsigned long long a,
                                     unsigned long long b) {
    asm("fma.rn.f32x2 %0, %1, %2, %0;" : "+l"(acc) : "l"(a), "l"(b));
}
__device__ __forceinline__ float2 unpack2(unsigned long long v) {
    float lo, hi;
    asm("mov.b64 {%0, %1}, %2;" : "=f"(lo), "=f"(hi) : "l"(v));
    return make_float2(lo, hi);
}

__global__ __launch_bounds__(256)
void gemm_relu_res_kernel(const float* __restrict__ x,
                          const float* __restrict__ W,
                          float* __restrict__ out,
                          int n_rows) {
    extern __shared__ float smem[];
    float* Wt = smem;                              // [128][WT_LD]
    float* rowbuf = smem + DD * WT_LD;             // [WARPS][4][128]

    for (int idx = threadIdx.x; idx < DD * DD; idx += blockDim.x) {
        int j = idx & (DD - 1);
        int k = idx >> 7;
        Wt[k * WT_LD + j] = W[j * DD + k];
    }
    __syncthreads();

    const int warp = threadIdx.x >> 5;
    const int lane = threadIdx.x & 31;
    float* rb = rowbuf + warp * (ROWS_PER_WARP * DD);

    const int warps_total = gridDim.x * WARPS_PER_BLOCK;
    const int gwarp = blockIdx.x * WARPS_PER_BLOCK + warp;

    for (int r0 = gwarp * ROWS_PER_WARP; r0 < n_rows;
         r0 += warps_total * ROWS_PER_WARP) {

        __syncwarp();
        #pragma unroll
        for (int r = 0; r < ROWS_PER_WARP; r++) {
            int row = r0 + r;
            if (row < n_rows) {
                float4 v = *reinterpret_cast<const float4*>(
                    g_agg + (size_t)row * DD + lane * 4);
                *reinterpret_cast<float4*>(rb + r * DD + lane * 4) = v;
            }
        }
        __syncwarp();

        // acc[r] pairs: {out[lane*4], out[lane*4+1]} and {+2, +3}
        unsigned long long acc01[ROWS_PER_WARP] = {0ull, 0ull, 0ull, 0ull};
        unsigned long long acc23[ROWS_PER_WARP] = {0ull, 0ull, 0ull, 0ull};

        #pragma unroll 4
        for (int k = 0; k < DD; k += 4) {
            float4 a0 = *reinterpret_cast<const float4*>(rb + 0 * DD + k);
            float4 a1 = *reinterpret_cast<const float4*>(rb + 1 * DD + k);
            float4 a2 = *reinterpret_cast<const float4*>(rb + 2 * DD + k);
            float4 a3 = *reinterpret_cast<const float4*>(rb + 3 * DD + k);
            const float* pa[4] = {
                reinterpret_cast<const float*>(&a0),
                reinterpret_cast<const float*>(&a1),
                reinterpret_cast<const float*>(&a2),
                reinterpret_cast<const float*>(&a3)};

            #pragma unroll
            for (int kk = 0; kk < 4; kk++) {
                // w row loaded as 2 pre-packed f32x2 values
                ulonglong2 w = *reinterpret_cast<const ulonglong2*>(
                    Wt + (k + kk) * WT_LD + lane * 4);
                #pragma unroll
                for (int r = 0; r < ROWS_PER_WARP; r++) {
                    unsigned long long bb = pack_dup(pa[r][kk]);
                    fma2(acc01[r], w.x, bb);
                    fma2(acc23[r], w.y, bb);
                }
            }
        }

        #pragma unroll
        for (int r = 0; r < ROWS_PER_WARP; r++) {
            int row = r0 + r;
            if (row >= n_rows) break;
            float2 p01 = unpack2(acc01[r]);
            float2 p23 = unpack2(acc23[r]);
            float4 xr = *reinterpret_cast<const float4*>(
                x + (size_t)row * DD + lane * 4);
            float4 res;
            res.x = fmaxf(p01.x, 0.f) + xr.x;
            res.y = fmaxf(p01.y, 0.f) + xr.y;
            res.z = fmaxf(p23.x, 0.f) + xr.z;
            res.w = fmaxf(p23.y, 0.f) + xr.w;
            *reinterpret_cast<float4*>(out + (size_t)row * DD + lane * 4) = res;
        }
    }
}

// ---------------------------------------------------------------------------
// Launch
// ---------------------------------------------------------------------------
extern "C" void kernel_launch(void* const* d_in, const int* in_sizes, int n_in,
                              void* d_out, int out_size) {
    const float* x   = (const float*)d_in[0];      // [N, 128] f32
    const float* W   = (const float*)d_in[1];      // [128, 128] f32
    const int*   src = (const int*)d_in[2];        // [E] int32
    const int*   dst = (const int*)d_in[3];        // [E] int32
    float*       out = (float*)d_out;              // [N, 128] f32

    const int n_nodes = in_sizes[0] / DD;
    const int n_edges = in_sizes[2];

    // 1) zero agg
    zero_agg_kernel<<<592, 256>>>(n_nodes * DD / 4);

    // 2) scatter-add, 8 edges per warp-batch, grid-stride (~2 batches/warp)
    int nwarps_needed = (n_edges + EPW - 1) / EPW;
    int blocks = (nwarps_needed / 2 + 7) / 8;          // 8 warps per block
    if (blocks > 6144) blocks = 6144;
    if (blocks < 148) blocks = 148;
    scatter_add_kernel<<<blocks, 256>>>(x, src, dst, n_edges, n_nodes);

    // 3) fused GEMM + relu + residual (f32x2 packed FMA)
    size_t smem = (DD * WT_LD + WARPS_PER_BLOCK * ROWS_PER_WARP * DD) * sizeof(float);
    cudaFuncSetAttribute(gemm_relu_res_kernel,
                         cudaFuncAttributeMaxDynamicSharedMemorySize, (int)smem);
    gemm_relu_res_kernel<<<296, 256, smem>>>(x, W, out, n_nodes);
}

// round 7
// speedup vs baseline: 1.3986x; 1.0019x over previous
#include <cuda_runtime.h>

#define DD 128
#define NODES_MAX 50000

// Scratch: aggregated neighbor features (allocation-free rule -> __device__ global)
__device__ float g_agg[NODES_MAX * DD];

// ---------------------------------------------------------------------------
// Kernel 1: zero the aggregation buffer
// ---------------------------------------------------------------------------
__global__ void zero_agg_kernel(int n4) {
    float4 z = make_float4(0.f, 0.f, 0.f, 0.f);
    for (int i = blockIdx.x * blockDim.x + threadIdx.x; i < n4;
         i += gridDim.x * blockDim.x) {
        reinterpret_cast<float4*>(g_agg)[i] = z;
    }
}

// ---------------------------------------------------------------------------
// Kernel 2: scatter-add  agg[dst] += x[src]
// Grid-stride; each warp processes batches of 8 edges:
//  - 16 broadcast index loads hoisted
//  - 8 independent LDG.128 row-gathers in flight (MLP=8)
//  - 8 float4 RED atomics (fire-and-forget)
// ---------------------------------------------------------------------------
#define EPW 8   // edges per warp-batch

__global__ __launch_bounds__(256)
void scatter_add_kernel(const float* __restrict__ x,
                        const int* __restrict__ src,
                        const int* __restrict__ dst,
                        int n_edges, int n_nodes) {
    const int lane = threadIdx.x & 31;
    const int gwarp = (blockIdx.x * blockDim.x + threadIdx.x) >> 5;
    const int nwarps = (gridDim.x * blockDim.x) >> 5;

    for (int base = gwarp * EPW; base < n_edges; base += nwarps * EPW) {
        const int cnt = min(EPW, n_edges - base);

        int s[EPW], d[EPW];
        #pragma unroll
        for (int i = 0; i < EPW; i++) {
            int e = (i < cnt) ? (base + i) : base;
            s[i] = __ldg(&src[e]);   // broadcast (1 sector)
            d[i] = __ldg(&dst[e]);
            if ((unsigned)s[i] >= (unsigned)n_nodes) s[i] = 0;  // fail-soft
        }

        float4 v[EPW];
        #pragma unroll
        for (int i = 0; i < EPW; i++) {
            v[i] = __ldg(reinterpret_cast<const float4*>(
                       x + (size_t)s[i] * DD) + lane);
        }

        #pragma unroll
        for (int i = 0; i < EPW; i++) {
            if (i < cnt && (unsigned)d[i] < (unsigned)n_nodes) {
                atomicAdd(reinterpret_cast<float4*>(
                              g_agg + (size_t)d[i] * DD) + lane, v[i]);
            }
        }
    }
}

// ---------------------------------------------------------------------------
// Kernel 3: out = relu(agg @ W^T) + x   with packed fma.rn.f32x2
// Wt[k][j] in smem (pad 132). w float4 rows reinterpret directly as two
// pre-packed f32x2 operands; broadcast scalar packed once per (row,kk).
// ---------------------------------------------------------------------------
#define WT_LD 132
#define WARPS_PER_BLOCK 8
#define ROWS_PER_WARP 4

__device__ __forceinline__ unsigned long long pack_dup(float b) {
    unsigned long long r;
    asm("mov.b64 %0, {%1, %1};" : "=l"(r) : "f"(b));
    return r;
}
__device__ __forceinline__ void fma2(unsigned long long& acc,
                                     unsigned long long a,
                                     unsigned long long b) {
    asm("fma.rn.f32x2 %0, %1, %2, %0;" : "+l"(acc) : "l"(a), "l"(b));
}
__device__ __forceinline__ float2 unpack2(unsigned long long v) {
    float lo, hi;
    asm("mov.b64 {%0, %1}, %2;" : "=f"(lo), "=f"(hi) : "l"(v));
    return make_float2(lo, hi);
}

__global__ __launch_bounds__(256)
void gemm_relu_res_kernel(const float* __restrict__ x,
                          const float* __restrict__ W,
                          float* __restrict__ out,
                          int n_rows) {
    extern __shared__ float smem[];
    float* Wt = smem;                              // [128][WT_LD]
    float* rowbuf = smem + DD * WT_LD;             // [WARPS][4][128]

    for (int idx = threadIdx.x; idx < DD * DD; idx += blockDim.x) {
        int j = idx & (DD - 1);
        int k = idx >> 7;
        Wt[k * WT_LD + j] = W[j * DD + k];
    }
    __syncthreads();

    const int warp = threadIdx.x >> 5;
    const int lane = threadIdx.x & 31;
    float* rb = rowbuf + warp * (ROWS_PER_WARP * DD);

    const int warps_total = gridDim.x * WARPS_PER_BLOCK;
    const int gwarp = blockIdx.x * WARPS_PER_BLOCK + warp;

    for (int r0 = gwarp * ROWS_PER_WARP; r0 < n_rows;
         r0 += warps_total * ROWS_PER_WARP) {

        __syncwarp();
        #pragma unroll
        for (int r = 0; r < ROWS_PER_WARP; r++) {
            int row = r0 + r;
            if (row < n_rows) {
                float4 v = *reinterpret_cast<const float4*>(
                    g_agg + (size_t)row * DD + lane * 4);
                *reinterpret_cast<float4*>(rb + r * DD + lane * 4) = v;
            }
        }
        __syncwarp();

        // acc[r] pairs: {out[lane*4], out[lane*4+1]} and {+2, +3}
        unsigned long long acc01[ROWS_PER_WARP] = {0ull, 0ull, 0ull, 0ull};
        unsigned long long acc23[ROWS_PER_WARP] = {0ull, 0ull, 0ull, 0ull};

        #pragma unroll 4
        for (int k = 0; k < DD; k += 4) {
            float4 a0 = *reinterpret_cast<const float4*>(rb + 0 * DD + k);
            float4 a1 = *reinterpret_cast<const float4*>(rb + 1 * DD + k);
            float4 a2 = *reinterpret_cast<const float4*>(rb + 2 * DD + k);
            float4 a3 = *reinterpret_cast<const float4*>(rb + 3 * DD + k);
            const float* pa[4] = {
                reinterpret_cast<const float*>(&a0),
                reinterpret_cast<const float*>(&a1),
                reinterpret_cast<const float*>(&a2),
                reinterpret_cast<const float*>(&a3)};

            #pragma unroll
            for (int kk = 0; kk < 4; kk++) {
                // w row loaded as 2 pre-packed f32x2 values
                ulonglong2 w = *reinterpret_cast<const ulonglong2*>(
                    Wt + (k + kk) * WT_LD + lane * 4);
                #pragma unroll
                for (int r = 0; r < ROWS_PER_WARP; r++) {
                    unsigned long long bb = pack_dup(pa[r][kk]);
                    fma2(acc01[r], w.x, bb);
                    fma2(acc23[r], w.y, bb);
                }
            }
        }

        #pragma unroll
        for (int r = 0; r < ROWS_PER_WARP; r++) {
            int row = r0 + r;
            if (row >= n_rows) break;
            float2 p01 = unpack2(acc01[r]);
            float2 p23 = unpack2(acc23[r]);
            float4 xr = *reinterpret_cast<const float4*>(
                x + (size_t)row * DD + lane * 4);
            float4 res;
            res.x = fmaxf(p01.x, 0.f) + xr.x;
            res.y = fmaxf(p01.y, 0.f) + xr.y;
            res.z = fmaxf(p23.x, 0.f) + xr.z;
            res.w = fmaxf(p23.y, 0.f) + xr.w;
            *reinterpret_cast<float4*>(out + (size_t)row * DD + lane * 4) = res;
        }
    }
}

// ---------------------------------------------------------------------------
// Launch
// ---------------------------------------------------------------------------
extern "C" void kernel_launch(void* const* d_in, const int* in_sizes, int n_in,
                              void* d_out, int out_size) {
    const float* x   = (const float*)d_in[0];      // [N, 128] f32
    const float* W   = (const float*)d_in[1];      // [128, 128] f32
    const int*   src = (const int*)d_in[2];        // [E] int32
    const int*   dst = (const int*)d_in[3];        // [E] int32
    float*       out = (float*)d_out;              // [N, 128] f32

    const int n_nodes = in_sizes[0] / DD;
    const int n_edges = in_sizes[2];

    // 1) zero agg
    zero_agg_kernel<<<592, 256>>>(n_nodes * DD / 4);

    // 2) scatter-add, 8 edges per warp-batch, grid-stride (~2 batches/warp)
    int nwarps_needed = (n_edges + EPW - 1) / EPW;
    int blocks = (nwarps_needed / 2 + 7) / 8;          // 8 warps per block
    if (blocks > 6144) blocks = 6144;
    if (blocks < 148) blocks = 148;
    scatter_add_kernel<<<blocks, 256>>>(x, src, dst, n_edges, n_nodes);

    // 3) fused GEMM + relu + residual (f32x2 packed FMA)
    size_t smem = (DD * WT_LD + WARPS_PER_BLOCK * ROWS_PER_WARP * DD) * sizeof(float);
    cudaFuncSetAttribute(gemm_relu_res_kernel,
                         cudaFuncAttributeMaxDynamicSharedMemorySize, (int)smem);
    gemm_relu_res_kernel<<<296, 256, smem>>>(x, W, out, n_nodes);
}